// round 13
// baseline (speedup 1.0000x reference)
#include <cuda_runtime.h>
#include <cuda_bf16.h>
#include <cstdint>

#define DINL __device__ __forceinline__

// pre-rounded tf32 weights: [pass 2][tap 9][n=co 64][128B]
// 128B row = 32 tf32 (k=ci of pass); 8 x 16B granules, granule g stored at (g ^ (n&7))
__device__ __align__(16) unsigned char g_wsw[2 * 9 * 64 * 128];

constexpr uint32_t AROWSZ = 130 * 128;           // 16640 B per staged input row
constexpr uint32_t SA    = 0;                    // A ping-pong: 2 x 16640 = 33280
constexpr uint32_t SBUF  = 33280;                // B stages: 6 x 8192 = 49152
constexpr uint32_t SBAR  = 33280 + 49152;        // 82432
constexpr uint32_t SMEMSZ = SBAR + 96;           // 12 B-mbarriers

// ---------------- ptx helpers ----------------
DINL uint32_t s2u(const void* p){uint32_t a;asm("{.reg .u64 t; cvta.to.shared.u64 t,%1; cvt.u32.u64 %0,t;}":"=r"(a):"l"(p));return a;}
DINL void bar_init(uint32_t a,uint32_t c){asm volatile("mbarrier.init.shared.b64 [%0],%1;"::"r"(a),"r"(c):"memory");}
DINL void bar_arrive(uint32_t a){asm volatile("mbarrier.arrive.shared.b64 _,[%0];"::"r"(a):"memory");}
DINL void bar_expect_tx(uint32_t a,uint32_t b){asm volatile("mbarrier.arrive.expect_tx.shared.b64 _,[%0],%1;"::"r"(a),"r"(b):"memory");}
DINL void bar_wait(uint32_t a,uint32_t ph){
  uint32_t done;
  asm volatile("{\n\t"
               ".reg .pred p;\n\t"
               "mbarrier.try_wait.parity.acquire.cta.shared::cta.b64 p,[%1],%2;\n\t"
               "selp.b32 %0,1,0,p;\n\t"
               "}"
               :"=r"(done):"r"(a),"r"(ph):"memory");
  if(!done){
    asm volatile("{\n\t"
                 ".reg .pred P1;\n\t"
                 "WAIT_LOOP_%=:\n\t"
                 "mbarrier.try_wait.parity.acquire.cta.shared::cta.b64 P1,[%0],%1,0x989680;\n\t"
                 "@P1 bra.uni WAIT_DONE_%=;\n\t"
                 "bra.uni WAIT_LOOP_%=;\n\t"
                 "WAIT_DONE_%=:\n\t"
                 "}"
                 ::"r"(a),"r"(ph):"memory");
  }
}
DINL void bulk_cp(uint32_t dst,const void* src,uint32_t bytes,uint32_t mbar){
  asm volatile("cp.async.bulk.shared::cluster.global.mbarrier::complete_tx::bytes [%0],[%1],%2,[%3];"
               ::"r"(dst),"l"(src),"r"(bytes),"r"(mbar):"memory");
}
DINL void ldsm4(uint32_t* r, uint32_t a){
  asm volatile("ldmatrix.sync.aligned.m8n8.x4.shared.b16 {%0,%1,%2,%3},[%4];"
               :"=r"(r[0]),"=r"(r[1]),"=r"(r[2]),"=r"(r[3]):"r"(a));
}
DINL void mma(float* c, const uint32_t* a, uint32_t b0, uint32_t b1){
  asm volatile("mma.sync.aligned.m16n8k8.row.col.f32.tf32.tf32.f32 "
               "{%0,%1,%2,%3},{%4,%5,%6,%7},{%8,%9},{%0,%1,%2,%3};"
               :"+f"(c[0]),"+f"(c[1]),"+f"(c[2]),"+f"(c[3])
               :"r"(a[0]),"r"(a[1]),"r"(a[2]),"r"(a[3]),"r"(b0),"r"(b1));
}
DINL uint32_t f2tf(float f){uint32_t u;asm("cvt.rna.tf32.f32 %0,%1;":"=r"(u):"f"(f));return u;}

// ---------------- weight prep: tf32 round + swizzle ----------------
__global__ void prep_w(const float* __restrict__ wgt){
  int tap = blockIdx.x, co = threadIdx.x;   // <<<9, 64>>>
  uint32_t sw = (uint32_t)co & 7u;
  for (int p = 0; p < 2; p++){
    unsigned char* base = g_wsw + ((size_t)(p*9 + tap)*64 + co)*128;
    for (int k = 0; k < 32; k++){
      float v = wgt[co*576 + (p*32 + k)*9 + tap];
      uint32_t g = (uint32_t)(k >> 2), pos = ((uint32_t)k & 3u)*4u;
      *(uint32_t*)(base + ((g ^ sw) << 4) + pos) = f2tf(v);
    }
  }
}

// ---------------- staging helpers ----------------
DINL void store_unit(unsigned char* smem, uint32_t addr, uint32_t swz, const float* v){
  #pragma unroll
  for (int g = 0; g < 8; g++){
    uint4 q;
    q.x = f2tf(v[g*4 + 0]);
    q.y = f2tf(v[g*4 + 1]);
    q.z = f2tf(v[g*4 + 2]);
    q.w = f2tf(v[g*4 + 3]);
    *(uint4*)(smem + addr + ((((uint32_t)g) ^ swz) << 4)) = q;
  }
}
DINL void prefetch_row(const float* __restrict__ x, int b, int p, int y, int w,
                       bool valid, float* v){
  const float* xp = x + ((((size_t)b*64 + p*32)*256 + (size_t)(valid ? y : 0))*256) + (valid ? w : 0);
  #pragma unroll
  for (int ci = 0; ci < 32; ci++)
    v[ci] = valid ? xp[(size_t)ci * 65536] : 0.f;
}

// ---------------- main kernel ----------------
__global__ __launch_bounds__(256, 2)
void conv_mma(const float* __restrict__ x,
              const float* __restrict__ bias,
              float* __restrict__ out)
{
  extern __shared__ __align__(128) unsigned char smem[];
  const uint32_t sb = s2u(smem);
  const int tid = threadIdx.x, wid = tid >> 5, lane = tid & 31;
  const int half = blockIdx.x, h = blockIdx.y, b = blockIdx.z;

  // B barriers: FULL[0..5]@+0, EMPTY[0..5]@+48
  const uint32_t BARB = sb + SBAR;

  if (tid == 0){
    #pragma unroll
    for (int s = 0; s < 6; s++){
      bar_init(BARB + s*8, 1);            // B full: tx-based
      bar_init(BARB + 48 + s*8, 4);       // B empty: 4 compute warps (lane 0)
    }
  }
  __syncthreads();
  if (tid == 0){
    #pragma unroll
    for (int s = 0; s < 6; s++){
      bar_expect_tx(BARB + s*8, 8192u);
      bulk_cp(sb + SBUF + (uint32_t)s*8192u, g_wsw + (size_t)s*8192, 8192u, BARB + s*8);
    }
  }

  float acc[2][8][4];
  #pragma unroll
  for (int i = 0; i < 2; i++)
    #pragma unroll
    for (int j = 0; j < 8; j++)
      #pragma unroll
      for (int k = 0; k < 4; k++) acc[i][j][k] = 0.f;

  // lane-dependent compute constants
  const uint32_t s0     = (uint32_t)(wid*32) + (uint32_t)(lane & 15);  // A slot base
  const uint32_t gha    = (uint32_t)(lane >> 4);                        // A granule select
  const uint32_t co_off = (uint32_t)((lane & 7) + (((lane >> 4) & 1) << 3));
  const uint32_t eb     = (uint32_t)(((lane >> 3) & 1) ^ (lane & 7));   // B granule xor key

  // staging state (wid >= 4 only)
  const int wt = tid - 128;                         // 0..127
  const bool isedge = (wt == 0 || wt == 127);
  float vmain[32], vedge[32];

  if (wid >= 4){
    // prologue: prefetch row 0 (r=0: p=0, khr=0, y=h-1)
    int y = h - 1;
    bool vy = (unsigned)y < 256u;
    prefetch_row(x, b, 0, y, half*128 + wt, vy, vmain);        // s=wt+1 -> w=half*128+wt
    if (isedge){
      int s = (wt == 0) ? 0 : 129;
      int w = half*128 + s - 1;
      bool ok = vy && ((unsigned)w < 256u);
      prefetch_row(x, b, 0, y, w, ok, vedge);
    }
  }

  // 7 steps: staging stores row 'step' (prefetched), prefetches row 'step+1';
  //          compute consumes row 'step-1'.
  #pragma unroll 1
  for (int step = 0; step < 7; step++){
    if (wid >= 4){
      if (step < 6){
        const int r = step;
        const uint32_t Abase = SA + (uint32_t)(r & 1)*AROWSZ;
        store_unit(smem, Abase + (uint32_t)(wt + 1)*128u, (uint32_t)(wt + 1) & 7u, vmain);
        if (isedge){
          int s = (wt == 0) ? 0 : 129;
          store_unit(smem, Abase + (uint32_t)s*128u, (uint32_t)s & 7u, vedge);
        }
      }
      if (step < 5){
        const int rn = step + 1;                    // next row to prefetch
        const int p = (rn >= 3) ? 1 : 0;
        const int khr = rn - 3*p;
        int y = h + khr - 1;
        bool vy = (unsigned)y < 256u;
        prefetch_row(x, b, p, y, half*128 + wt, vy, vmain);
        if (isedge){
          int s = (wt == 0) ? 0 : 129;
          int w = half*128 + s - 1;
          bool ok = vy && ((unsigned)w < 256u);
          prefetch_row(x, b, p, y, w, ok, vedge);
        }
      }
      // B refiller: taps {3*step+3 .. 3*step+5}, gated on consumers of it-6
      // (which execute during THIS step) -> no cross-step deadlock.
      if (tid == 129 && step >= 1 && step <= 4){
        #pragma unroll 1
        for (int j = 0; j < 3; j++){
          int it = 3*step + 3 + j;
          if (it < 18){
            int st = it % 6;
            bar_wait(BARB + 48u + (uint32_t)st*8u, (uint32_t)(((it - 6)/6) & 1));
            bar_expect_tx(BARB + (uint32_t)st*8u, 8192u);
            bulk_cp(sb + SBUF + (uint32_t)st*8192u, g_wsw + (size_t)it*8192, 8192u,
                    BARB + (uint32_t)st*8u);
          }
        }
      }
    }

    if (wid < 4 && step >= 1){
      // ---------------- compute warps (0-3): consume row 'step-1' ----------------
      const int r = step - 1;
      const uint32_t Aslot = sb + SA + (uint32_t)(r & 1)*AROWSZ;

      #pragma unroll 1
      for (int kw = 0; kw < 3; kw++){
        const int it = r*3 + kw;               // linear tap-pass index 0..17
        const int st = it % 6;
        const uint32_t fullb  = BARB + (uint32_t)st*8u;
        const uint32_t emptyb = BARB + 48u + (uint32_t)st*8u;
        bar_wait(fullb, (uint32_t)((it/6) & 1));

        const uint32_t arow = s0 + (uint32_t)kw;
        const uint32_t Aa0  = Aslot + arow*128u;
        const uint32_t ea   = gha ^ (arow & 7u);
        const uint32_t Bt   = sb + SBUF + (uint32_t)st*8192u + co_off*128u;
        #pragma unroll
        for (int ks = 0; ks < 4; ks++){
          const uint32_t bofs = (uint32_t)(((2*ks) ^ (int)eb) << 4);
          uint32_t br[16];
          ldsm4(br + 0,  Bt + bofs);
          ldsm4(br + 4,  Bt + 2048u + bofs);
          ldsm4(br + 8,  Bt + 4096u + bofs);
          ldsm4(br + 12, Bt + 6144u + bofs);
          const uint32_t aofs = (uint32_t)(((2*ks) ^ (int)ea) << 4);
          #pragma unroll
          for (int mf = 0; mf < 2; mf++){
            uint32_t ar[4];
            ldsm4(ar, Aa0 + (uint32_t)mf*2048u + aofs);
            #pragma unroll
            for (int nf = 0; nf < 8; nf++)
              mma(acc[mf][nf], ar, br[nf*2], br[nf*2 + 1]);
          }
        }
        if (lane == 0) bar_arrive(emptyb);
      }
    }

    __syncthreads();   // row handoff: producer/consumer fence + buffer swap
  }

  // ---- epilogue ----
  if (wid < 4){
    #pragma unroll
    for (int mf = 0; mf < 2; mf++){
      #pragma unroll
      for (int nf = 0; nf < 8; nf++){
        int co = nf*8 + 2*(lane & 3);
        int wo = half*128 + wid*32 + mf*16 + (lane >> 2);
        float b0 = bias[co], b1 = bias[co + 1];
        size_t o0 = (((size_t)b*64 + co)*256 + h)*256 + wo;
        out[o0]             = acc[mf][nf][0] + b0;
        out[o0 + 65536]     = acc[mf][nf][1] + b1;
        out[o0 + 8]         = acc[mf][nf][2] + b0;
        out[o0 + 65536 + 8] = acc[mf][nf][3] + b1;
      }
    }
  }
}

// ---------------- launch ----------------
extern "C" void kernel_launch(void* const* d_in, const int* in_sizes, int n_in,
                              void* d_out, int out_size)
{
  (void)in_sizes; (void)n_in; (void)out_size;
  const float* x    = (const float*)d_in[0];
  const float* wgt  = (const float*)d_in[1];
  const float* bias = (const float*)d_in[2];
  float* out        = (float*)d_out;

  cudaFuncSetAttribute(conv_mma, cudaFuncAttributeMaxDynamicSharedMemorySize, SMEMSZ);

  prep_w<<<9, 64>>>(wgt);
  dim3 grid(2, 256, 16);   // (w-half, h, b) = 8192 CTAs
  conv_mma<<<grid, 256, SMEMSZ>>>(x, bias, out);
}

// round 14
// speedup vs baseline: 1.4164x; 1.4164x over previous
#include <cuda_runtime.h>
#include <cuda_bf16.h>
#include <cstdint>

#define DINL __device__ __forceinline__

// pre-rounded tf32 weights: [pass 2][tap 9][n=co 64][128B]
// 128B row = 32 tf32 (k=ci of pass); 8 x 16B granules, granule g stored at (g ^ (n&7))
__device__ __align__(16) unsigned char g_wsw[2 * 9 * 64 * 128];

constexpr uint32_t AROWSZ = 130 * 128;           // 16640 B per staged input row
constexpr uint32_t SA    = 0;                    // A ping-pong: 2 x 16640 = 33280
constexpr uint32_t SBUF  = 33280;                // B stages: 6 x 8192 = 49152
constexpr uint32_t SBAR  = 33280 + 49152;        // 82432
constexpr uint32_t SMEMSZ = SBAR + 96;           // 12 B-mbarriers

// ---------------- ptx helpers ----------------
DINL uint32_t s2u(const void* p){uint32_t a;asm("{.reg .u64 t; cvta.to.shared.u64 t,%1; cvt.u32.u64 %0,t;}":"=r"(a):"l"(p));return a;}
DINL void bar_init(uint32_t a,uint32_t c){asm volatile("mbarrier.init.shared.b64 [%0],%1;"::"r"(a),"r"(c):"memory");}
DINL void bar_arrive(uint32_t a){asm volatile("mbarrier.arrive.shared.b64 _,[%0];"::"r"(a):"memory");}
DINL void bar_expect_tx(uint32_t a,uint32_t b){asm volatile("mbarrier.arrive.expect_tx.shared.b64 _,[%0],%1;"::"r"(a),"r"(b):"memory");}
DINL void bar_wait(uint32_t a,uint32_t ph){
  uint32_t done;
  asm volatile("{\n\t"
               ".reg .pred p;\n\t"
               "mbarrier.try_wait.parity.acquire.cta.shared::cta.b64 p,[%1],%2;\n\t"
               "selp.b32 %0,1,0,p;\n\t"
               "}"
               :"=r"(done):"r"(a),"r"(ph):"memory");
  if(!done){
    asm volatile("{\n\t"
                 ".reg .pred P1;\n\t"
                 "WAIT_LOOP_%=:\n\t"
                 "mbarrier.try_wait.parity.acquire.cta.shared::cta.b64 P1,[%0],%1,0x989680;\n\t"
                 "@P1 bra.uni WAIT_DONE_%=;\n\t"
                 "bra.uni WAIT_LOOP_%=;\n\t"
                 "WAIT_DONE_%=:\n\t"
                 "}"
                 ::"r"(a),"r"(ph):"memory");
  }
}
DINL void bulk_cp(uint32_t dst,const void* src,uint32_t bytes,uint32_t mbar){
  asm volatile("cp.async.bulk.shared::cluster.global.mbarrier::complete_tx::bytes [%0],[%1],%2,[%3];"
               ::"r"(dst),"l"(src),"r"(bytes),"r"(mbar):"memory");
}
DINL void ldsm4(uint32_t* r, uint32_t a){
  asm volatile("ldmatrix.sync.aligned.m8n8.x4.shared.b16 {%0,%1,%2,%3},[%4];"
               :"=r"(r[0]),"=r"(r[1]),"=r"(r[2]),"=r"(r[3]):"r"(a));
}
DINL void mma(float* c, const uint32_t* a, uint32_t b0, uint32_t b1){
  asm volatile("mma.sync.aligned.m16n8k8.row.col.f32.tf32.tf32.f32 "
               "{%0,%1,%2,%3},{%4,%5,%6,%7},{%8,%9},{%0,%1,%2,%3};"
               :"+f"(c[0]),"+f"(c[1]),"+f"(c[2]),"+f"(c[3])
               :"r"(a[0]),"r"(a[1]),"r"(a[2]),"r"(a[3]),"r"(b0),"r"(b1));
}
DINL uint32_t f2tf(float f){uint32_t u;asm("cvt.rna.tf32.f32 %0,%1;":"=r"(u):"f"(f));return u;}

// ---------------- weight prep: tf32 round + swizzle ----------------
__global__ void prep_w(const float* __restrict__ wgt){
  int tap = blockIdx.x, co = threadIdx.x;   // <<<9, 64>>>
  uint32_t sw = (uint32_t)co & 7u;
  for (int p = 0; p < 2; p++){
    unsigned char* base = g_wsw + ((size_t)(p*9 + tap)*64 + co)*128;
    for (int k = 0; k < 32; k++){
      float v = wgt[co*576 + (p*32 + k)*9 + tap];
      uint32_t g = (uint32_t)(k >> 2), pos = ((uint32_t)k & 3u)*4u;
      *(uint32_t*)(base + ((g ^ sw) << 4) + pos) = f2tf(v);
    }
  }
}

// ---------------- staging helper: one slot (32 tf32, swizzled) ----------------
DINL void store_unit(unsigned char* smem, uint32_t addr, uint32_t swz, const float* v){
  #pragma unroll
  for (int g = 0; g < 8; g++){
    uint4 q;
    q.x = f2tf(v[g*4 + 0]);
    q.y = f2tf(v[g*4 + 1]);
    q.z = f2tf(v[g*4 + 2]);
    q.w = f2tf(v[g*4 + 3]);
    *(uint4*)(smem + addr + ((((uint32_t)g) ^ swz) << 4)) = q;
  }
}

// ---------------- main kernel ----------------
__global__ __launch_bounds__(256, 2)
void conv_mma(const float* __restrict__ x,
              const float* __restrict__ bias,
              float* __restrict__ out)
{
  extern __shared__ __align__(128) unsigned char smem[];
  const uint32_t sb = s2u(smem);
  const int tid = threadIdx.x, wid = tid >> 5, lane = tid & 31;
  const int half = blockIdx.x, h = blockIdx.y, b = blockIdx.z;

  // B barriers: FULL[0..5]@+0, EMPTY[0..5]@+48
  const uint32_t BARB = sb + SBAR;

  if (tid == 0){
    #pragma unroll
    for (int s = 0; s < 6; s++){
      bar_init(BARB + s*8, 1);            // B full: tx-based
      bar_init(BARB + 48 + s*8, 4);       // B empty: 4 compute warps (lane 0)
    }
  }
  __syncthreads();
  if (tid == 0){
    #pragma unroll
    for (int s = 0; s < 6; s++){
      bar_expect_tx(BARB + s*8, 8192u);
      bulk_cp(sb + SBUF + (uint32_t)s*8192u, g_wsw + (size_t)s*8192, 8192u, BARB + s*8);
    }
  }

  float acc[2][8][4];
  #pragma unroll
  for (int i = 0; i < 2; i++)
    #pragma unroll
    for (int j = 0; j < 8; j++)
      #pragma unroll
      for (int k = 0; k < 4; k++) acc[i][j][k] = 0.f;

  // lane-dependent compute constants
  const uint32_t s0     = (uint32_t)(wid*32) + (uint32_t)(lane & 15);  // A slot base
  const uint32_t gha    = (uint32_t)(lane >> 4);                        // A granule select
  const uint32_t co_off = (uint32_t)((lane & 7) + (((lane >> 4) & 1) << 3));
  const uint32_t eb     = (uint32_t)(((lane >> 3) & 1) ^ (lane & 7));   // B granule xor key

  // 7 steps: at step s, staging warps fill row s into buf[s&1],
  //          compute warps consume row s-1 from buf[(s-1)&1].
  #pragma unroll 1
  for (int step = 0; step < 7; step++){
    if (wid >= 4){
      if (step < 6){
        // ---------------- staging warps (4-7): fill row 'step' ----------------
        const int r = step;                       // r = p*3 + khr
        const int p = (r >= 3) ? 1 : 0;
        const int khr = r - 3*p;
        const uint32_t Abase = SA + (uint32_t)(r & 1)*AROWSZ;
        const int wt = tid - 128;                 // 0..127
        const int y = h + khr - 1;
        const bool vy = (unsigned)y < 256u;
        {
          int s = wt + 1;                         // slots 1..128: w always in-range
          int w = half*128 + s - 1;
          const float* xp = x + ((((size_t)b*64 + p*32)*256 + (size_t)(vy ? y : 0))*256) + w;
          float v[32];
          #pragma unroll
          for (int ci = 0; ci < 32; ci++)
            v[ci] = vy ? xp[(size_t)ci * 65536] : 0.f;
          store_unit(smem, Abase + (uint32_t)s*128u, (uint32_t)s & 7u, v);
        }
        if (wt == 0 || wt == 127){                // edge slots 0 and 129
          int s = (wt == 0) ? 0 : 129;
          int w = half*128 + s - 1;
          bool ok = vy && ((unsigned)w < 256u);
          const float* xp = x + ((((size_t)b*64 + p*32)*256 + (size_t)(ok ? y : 0))*256) + (ok ? w : 0);
          float v[32];
          #pragma unroll
          for (int ci = 0; ci < 32; ci++)
            v[ci] = ok ? xp[(size_t)ci * 65536] : 0.f;
          store_unit(smem, Abase + (uint32_t)s*128u, (uint32_t)s & 7u, v);
        }
      }
      // B refiller (tid 128, after staging stores): refill taps 3*step+3..3*step+5.
      // Gate on consumers of tap it-6, which arrive during THIS step (compute is on
      // taps 3*step-3..3*step-1) -> resolves before the step barrier, no deadlock.
      if (tid == 128 && step >= 1 && step <= 4){
        #pragma unroll 1
        for (int j = 0; j < 3; j++){
          int it = 3*step + 3 + j;
          if (it < 18){
            int st = it % 6;
            bar_wait(BARB + 48u + (uint32_t)st*8u, (uint32_t)(((it - 6)/6) & 1));
            bar_expect_tx(BARB + (uint32_t)st*8u, 8192u);
            bulk_cp(sb + SBUF + (uint32_t)st*8192u, g_wsw + (size_t)it*8192, 8192u,
                    BARB + (uint32_t)st*8u);
          }
        }
      }
    }

    if (wid < 4 && step >= 1){
      // ---------------- compute warps (0-3): consume row 'step-1' ----------------
      const int r = step - 1;
      const uint32_t Aslot = sb + SA + (uint32_t)(r & 1)*AROWSZ;

      #pragma unroll 1
      for (int kw = 0; kw < 3; kw++){
        const int it = r*3 + kw;               // linear tap-pass index 0..17
        const int st = it % 6;
        const uint32_t fullb  = BARB + (uint32_t)st*8u;
        const uint32_t emptyb = BARB + 48u + (uint32_t)st*8u;
        bar_wait(fullb, (uint32_t)((it/6) & 1));

        const uint32_t arow = s0 + (uint32_t)kw;
        const uint32_t Aa0  = Aslot + arow*128u;
        const uint32_t ea   = gha ^ (arow & 7u);
        const uint32_t Bt   = sb + SBUF + (uint32_t)st*8192u + co_off*128u;
        #pragma unroll
        for (int ks = 0; ks < 4; ks++){
          const uint32_t bofs = (uint32_t)(((2*ks) ^ (int)eb) << 4);
          uint32_t br[16];
          ldsm4(br + 0,  Bt + bofs);
          ldsm4(br + 4,  Bt + 2048u + bofs);
          ldsm4(br + 8,  Bt + 4096u + bofs);
          ldsm4(br + 12, Bt + 6144u + bofs);
          const uint32_t aofs = (uint32_t)(((2*ks) ^ (int)ea) << 4);
          #pragma unroll
          for (int mf = 0; mf < 2; mf++){
            uint32_t ar[4];
            ldsm4(ar, Aa0 + (uint32_t)mf*2048u + aofs);
            #pragma unroll
            for (int nf = 0; nf < 8; nf++)
              mma(acc[mf][nf], ar, br[nf*2], br[nf*2 + 1]);
          }
        }
        if (lane == 0) bar_arrive(emptyb);
      }
    }

    __syncthreads();   // row handoff: producer/consumer fence + buffer swap
  }

  // ---- epilogue ----
  if (wid < 4){
    #pragma unroll
    for (int mf = 0; mf < 2; mf++){
      #pragma unroll
      for (int nf = 0; nf < 8; nf++){
        int co = nf*8 + 2*(lane & 3);
        int wo = half*128 + wid*32 + mf*16 + (lane >> 2);
        float b0 = bias[co], b1 = bias[co + 1];
        size_t o0 = (((size_t)b*64 + co)*256 + h)*256 + wo;
        out[o0]             = acc[mf][nf][0] + b0;
        out[o0 + 65536]     = acc[mf][nf][1] + b1;
        out[o0 + 8]         = acc[mf][nf][2] + b0;
        out[o0 + 65536 + 8] = acc[mf][nf][3] + b1;
      }
    }
  }
}

// ---------------- launch ----------------
extern "C" void kernel_launch(void* const* d_in, const int* in_sizes, int n_in,
                              void* d_out, int out_size)
{
  (void)in_sizes; (void)n_in; (void)out_size;
  const float* x    = (const float*)d_in[0];
  const float* wgt  = (const float*)d_in[1];
  const float* bias = (const float*)d_in[2];
  float* out        = (float*)d_out;

  cudaFuncSetAttribute(conv_mma, cudaFuncAttributeMaxDynamicSharedMemorySize, SMEMSZ);

  prep_w<<<9, 64>>>(wgt);
  dim3 grid(2, 256, 16);   // (w-half, h, b) = 8192 CTAs
  conv_mma<<<grid, 256, SMEMSZ>>>(x, bias, out);
}

// round 16
// speedup vs baseline: 1.7867x; 1.2614x over previous
#include <cuda_runtime.h>
#include <cstdint>

#define DINL __device__ __forceinline__

// Frag-packed tf32 weights: [pass 8][kw 3][kh 3][mf 4][lane 32][4 floats]
// (a0,a1,a2,a3 of mma.m16n8k8 packed contiguously per lane -> LDS.128)
__device__ __align__(16) unsigned char g_wA[8 * 18432];

constexpr uint32_t XROW   = 1056;            // 264 floats per (kh,ci) row; 264%32==8 -> conflict-free
constexpr uint32_t XSLAB  = 24 * XROW;       // 25344 B per pass (3 kh x 8 ci)
constexpr uint32_t SX     = 0;               // X double buffer: 2 x 25344
constexpr uint32_t SW     = 2 * XSLAB;       // 50688
constexpr uint32_t WSLAB  = 18432;           // W per pass
constexpr uint32_t SBAR   = SW + 2 * WSLAB;  // 87552
constexpr uint32_t SMEMSZ = SBAR + 32;       // XF0 XF1 WF0 WF1

// ---------------- ptx helpers ----------------
DINL uint32_t s2u(const void* p){uint32_t a;asm("{.reg .u64 t; cvta.to.shared.u64 t,%1; cvt.u32.u64 %0,t;}":"=r"(a):"l"(p));return a;}
DINL void bar_init(uint32_t a,uint32_t c){asm volatile("mbarrier.init.shared.b64 [%0],%1;"::"r"(a),"r"(c):"memory");}
DINL void bar_expect_tx(uint32_t a,uint32_t b){asm volatile("mbarrier.arrive.expect_tx.shared.b64 _,[%0],%1;"::"r"(a),"r"(b):"memory");}
DINL void bar_wait(uint32_t a,uint32_t ph){
  uint32_t done;
  asm volatile("{\n\t.reg .pred p;\n\t"
               "mbarrier.try_wait.parity.acquire.cta.shared::cta.b64 p,[%1],%2;\n\t"
               "selp.b32 %0,1,0,p;\n\t}"
               :"=r"(done):"r"(a),"r"(ph):"memory");
  if(!done){
    asm volatile("{\n\t.reg .pred P1;\n\t"
                 "WAIT_LOOP_%=:\n\t"
                 "mbarrier.try_wait.parity.acquire.cta.shared::cta.b64 P1,[%0],%1,0x989680;\n\t"
                 "@P1 bra.uni WAIT_DONE_%=;\n\t"
                 "bra.uni WAIT_LOOP_%=;\n\t"
                 "WAIT_DONE_%=:\n\t}"
                 ::"r"(a),"r"(ph):"memory");
  }
}
DINL void bulk_cp(uint32_t dst,const void* src,uint32_t bytes,uint32_t mbar){
  asm volatile("cp.async.bulk.shared::cluster.global.mbarrier::complete_tx::bytes [%0],[%1],%2,[%3];"
               ::"r"(dst),"l"(src),"r"(bytes),"r"(mbar):"memory");
}
DINL void lds128(uint32_t* r, uint32_t a){
  asm volatile("ld.shared.v4.b32 {%0,%1,%2,%3},[%4];"
               :"=r"(r[0]),"=r"(r[1]),"=r"(r[2]),"=r"(r[3]):"r"(a));
}
DINL uint32_t lds32(uint32_t a){
  uint32_t r; asm volatile("ld.shared.b32 %0,[%1];":"=r"(r):"r"(a)); return r;
}
DINL void mma(float* c, const uint32_t* a, uint32_t b0, uint32_t b1){
  asm volatile("mma.sync.aligned.m16n8k8.row.col.f32.tf32.tf32.f32 "
               "{%0,%1,%2,%3},{%4,%5,%6,%7},{%8,%9},{%0,%1,%2,%3};"
               :"+f"(c[0]),"+f"(c[1]),"+f"(c[2]),"+f"(c[3])
               :"r"(a[0]),"r"(a[1]),"r"(a[2]),"r"(a[3]),"r"(b0),"r"(b1));
}
DINL uint32_t f2tf(float f){uint32_t u;asm("cvt.rna.tf32.f32 %0,%1;":"=r"(u):"f"(f));return u;}

// ---------------- weight prep: frag-pack + tf32 round ----------------
// blockIdx.x = pass*9 + kw*3 + kh ; 128 threads = mf*32 + lane
__global__ void prep_w(const float* __restrict__ wgt){
  int blk = blockIdx.x;
  int pass = blk / 9, rem = blk % 9, kw = rem / 3, kh = rem % 3;
  int t = threadIdx.x;
  int mf = t >> 5, lane = t & 31;
  int g = lane >> 2, tt = lane & 3;
  uint32_t u[4];
  #pragma unroll
  for (int j = 0; j < 4; j++){
    int co = mf*16 + g + (j & 1)*8;
    int ci = pass*8 + tt + (j >> 1)*4;
    u[j] = f2tf(wgt[co*576 + ci*9 + kh*3 + kw]);
  }
  uint4 q; q.x = u[0]; q.y = u[1]; q.z = u[2]; q.w = u[3];
  *(uint4*)(g_wA + (size_t)blk*2048 + (size_t)mf*512 + (size_t)lane*16) = q;
}

// ---------------- main kernel ----------------
// CTA = (h, b): OUT^T[co 64][px 256]. 8 warps, warp w covers px w*32..w*32+31.
__global__ __launch_bounds__(256, 2)
void conv_mma(const float* __restrict__ x,
              const float* __restrict__ bias,
              float* __restrict__ out)
{
  extern __shared__ __align__(128) unsigned char smem[];
  const uint32_t sb = s2u(smem);
  const int tid = threadIdx.x, wid = tid >> 5, lane = tid & 31;
  const int g = lane >> 2, tt = lane & 3;
  const int h = blockIdx.x, b = blockIdx.y;

  const uint32_t XFB = sb + SBAR;        // XF[0], XF[1]
  const uint32_t WFB = sb + SBAR + 16;   // WF[0], WF[1]

  // zero the halo pads once (bytes 0..15 and 1040..1055 of every row, both buffers)
  if (tid < 96){
    int buf = tid / 48, rr = (tid % 48) >> 1, e = tid & 1;
    uint4 z = {0,0,0,0};
    *(uint4*)(smem + SX + (size_t)buf*XSLAB + (size_t)rr*XROW + (size_t)e*1040) = z;
  }
  if (tid == 0){
    bar_init(XFB, 1); bar_init(XFB + 8, 1);
    bar_init(WFB, 1); bar_init(WFB + 8, 1);
  }
  __syncthreads();

  const int kh_lo = (h == 0) ? 1 : 0;
  const int kh_hi = (h == 255) ? 2 : 3;
  const uint32_t xtx = (uint32_t)(kh_hi - kh_lo) * 8192u;

  // issuer lambdas (tid 0 only, never waits)
  auto issueX = [&](int p){
    uint32_t xb  = sb + SX + (uint32_t)(p & 1)*XSLAB;
    uint32_t bar = XFB + (uint32_t)(p & 1)*8u;
    bar_expect_tx(bar, xtx);
    for (int kh = kh_lo; kh < kh_hi; kh++)
      for (int ci = 0; ci < 8; ci++){
        const float* src = x + (((size_t)b*64 + p*8 + ci)*256 + (size_t)(h + kh - 1))*256;
        bulk_cp(xb + (uint32_t)(kh*8 + ci)*XROW + 16u, src, 1024u, bar);
      }
  };
  auto issueW = [&](int p){
    uint32_t bar = WFB + (uint32_t)(p & 1)*8u;
    bar_expect_tx(bar, 18432u);
    bulk_cp(sb + SW + (uint32_t)(p & 1)*WSLAB, g_wA + (size_t)p*WSLAB, 18432u, bar);
  };

  if (tid == 0){ issueX(0); issueW(0); issueX(1); issueW(1); }

  float acc[4][4][4];
  #pragma unroll
  for (int i = 0; i < 4; i++)
    #pragma unroll
    for (int j = 0; j < 4; j++)
      #pragma unroll
      for (int k = 0; k < 4; k++) acc[i][j][k] = 0.f;

  #pragma unroll 1
  for (int p = 0; p < 8; p++){
    // issue pass p+1: its buffer was consumed in pass p-1, which finished
    // before the __syncthreads we just passed -> race-free, no empty barriers.
    if (tid == 0 && p >= 1 && p <= 6){ issueX(p + 1); issueW(p + 1); }

    bar_wait(XFB + (uint32_t)(p & 1)*8u, (uint32_t)((p >> 1) & 1));
    bar_wait(WFB + (uint32_t)(p & 1)*8u, (uint32_t)((p >> 1) & 1));

    const uint32_t Xb = sb + SX + (uint32_t)(p & 1)*XSLAB;
    const uint32_t Wb = sb + SW + (uint32_t)(p & 1)*WSLAB;

    #pragma unroll
    for (int kw = 0; kw < 3; kw++){
      #pragma unroll 1
      for (int kh = kh_lo; kh < kh_hi; kh++){
        // A fragments: 4 x LDS.128 (frag-packed by prep_w)
        const uint32_t Aa = Wb + (uint32_t)(kw*3 + kh)*2048u + (uint32_t)lane*16u;
        uint32_t a[4][4];
        #pragma unroll
        for (int mf = 0; mf < 4; mf++) lds128(a[mf], Aa + (uint32_t)mf*512u);

        // B base: word = (kh*8 + tt)*264 + 4 + wid*32 + g + (kw-1)
        const uint32_t Baddr = Xb +
          ((uint32_t)(kh*8 + tt)*264u + 4u + (uint32_t)(wid*32) + (uint32_t)g
           + (uint32_t)kw - 1u)*4u;
        #pragma unroll
        for (int nf = 0; nf < 4; nf++){
          uint32_t b0 = lds32(Baddr + (uint32_t)nf*32u);
          uint32_t b1 = lds32(Baddr + (uint32_t)nf*32u + 4224u);  // +4 ci rows
          #pragma unroll
          for (int mf = 0; mf < 4; mf++)
            mma(acc[mf][nf], a[mf], b0, b1);
        }
      }
    }
    __syncthreads();   // pass handoff: all consumption of buf[p&1] complete
  }

  // ---- epilogue: OUT^T rows are coalesced ----
  #pragma unroll
  for (int mf = 0; mf < 4; mf++){
    int co = mf*16 + g;
    float bc0 = bias[co], bc8 = bias[co + 8];
    size_t base0 = (((size_t)b*64 + co)*256 + h)*256;
    #pragma unroll
    for (int nf = 0; nf < 4; nf++){
      int px = wid*32 + nf*8 + 2*tt;
      float2 v0, v1;
      v0.x = acc[mf][nf][0] + bc0; v0.y = acc[mf][nf][1] + bc0;
      v1.x = acc[mf][nf][2] + bc8; v1.y = acc[mf][nf][3] + bc8;
      *(float2*)(out + base0 + px) = v0;
      *(float2*)(out + base0 + (size_t)8*65536 + px) = v1;
    }
  }
}

// ---------------- launch ----------------
extern "C" void kernel_launch(void* const* d_in, const int* in_sizes, int n_in,
                              void* d_out, int out_size)
{
  (void)in_sizes; (void)n_in; (void)out_size;
  const float* x    = (const float*)d_in[0];
  const float* wgt  = (const float*)d_in[1];
  const float* bias = (const float*)d_in[2];
  float* out        = (float*)d_out;

  cudaFuncSetAttribute(conv_mma, cudaFuncAttributeMaxDynamicSharedMemorySize, SMEMSZ);

  prep_w<<<72, 128>>>(wgt);
  dim3 grid(256, 16);   // (h, b) = 4096 CTAs
  conv_mma<<<grid, 256, SMEMSZ>>>(x, bias, out);
}